// round 5
// baseline (speedup 1.0000x reference)
#include <cuda_runtime.h>
#include <cuda_bf16.h>

#define HID 64
#define NMAX 100352
#define EMAX 3210240

// ---------------- scratch (static device globals; no allocation) ----------------
__device__ int   g_deg[NMAX];
__device__ int   g_off[NMAX + 1];
__device__ int   g_bsum[512];
__device__ int   g_rank[EMAX];
__device__ int   g_adj[EMAX];
__device__ float g_spos[NMAX];
__device__ float g_sneg[NMAX];
__device__ __align__(16) float g_x4[NMAX * HID];                 // round-4 output (fp32)
__device__ __align__(16) __nv_bfloat16 g_h0[NMAX * HID];          // bf16 x buffers
__device__ __align__(16) __nv_bfloat16 g_h1[NMAX * HID];
__device__ __align__(16) __nv_bfloat16 g_h2[NMAX * HID];
__device__ float g_sumx[HID];
__device__ float g_c[1];

// exact bf16x2 -> float2 (bits<<16)
__device__ __forceinline__ float2 bf2_to_f2(unsigned u) {
    float2 r;
    r.x = __uint_as_float(u << 16);
    r.y = __uint_as_float(u & 0xFFFF0000u);
    return r;
}

// ---------------- init: zero counters + convert external fp32 x -> bf16 ----------------
__global__ void k_init(const float* __restrict__ x, int n) {
    int i = blockIdx.x * blockDim.x + threadIdx.x;
    int stride = gridDim.x * blockDim.x;
    for (int j = i; j < n; j += stride) {
        g_deg[j]  = 0;
        g_spos[j] = 0.f;
        g_sneg[j] = 0.f;
    }
    int n4 = n * (HID / 4);
    for (int j = i; j < n4; j += stride) {
        float4 f = ((const float4*)x)[j];
        __nv_bfloat162 a = __floats2bfloat162_rn(f.x, f.y);
        __nv_bfloat162 b = __floats2bfloat162_rn(f.z, f.w);
        uint2 u;
        u.x = *(unsigned*)&a;
        u.y = *(unsigned*)&b;
        ((uint2*)g_h0)[j] = u;
    }
    if (i < HID) g_sumx[i] = 0.f;
}

// ---------------- edge pass: degree histogram (returns rank) + p3 scalars ----------------
__global__ void k_hist(const int* __restrict__ src, const int* __restrict__ dst,
                       const float* __restrict__ attr, int E) {
    int i = blockIdx.x * blockDim.x + threadIdx.x;
    int stride = gridDim.x * blockDim.x;
    for (int e = i; e < E; e += stride) {
        int d = dst[e];
        g_rank[e] = atomicAdd(&g_deg[d], 1);
        float a = attr[e];
        int s = src[e];
        if (a >= 0.f) atomicAdd(&g_spos[s], a);
        else          atomicAdd(&g_sneg[s], -a);
    }
}

// ---------------- 3-kernel parallel exclusive scan over degrees ----------------
__global__ void k_scan1(int n) {
    __shared__ int wsum[8];
    int idx = blockIdx.x * 256 + threadIdx.x;
    int lane = threadIdx.x & 31, wid = threadIdx.x >> 5;
    int v = (idx < n) ? g_deg[idx] : 0;
    int x = v;
    #pragma unroll
    for (int o = 1; o < 32; o <<= 1) {
        int t = __shfl_up_sync(0xffffffffu, x, o);
        if (lane >= o) x += t;
    }
    if (lane == 31) wsum[wid] = x;
    __syncthreads();
    if (wid == 0) {
        int w = (lane < 8) ? wsum[lane] : 0;
        #pragma unroll
        for (int o = 1; o < 8; o <<= 1) {
            int t = __shfl_up_sync(0xffffffffu, w, o);
            if (lane >= o) w += t;
        }
        if (lane < 8) wsum[lane] = w;
    }
    __syncthreads();
    int pre = wid ? wsum[wid - 1] : 0;
    if (idx < n) g_off[idx] = pre + x - v;
    if (threadIdx.x == 255) g_bsum[blockIdx.x] = pre + x;
}

__global__ void k_scan2(int nb, int n) {
    __shared__ int wsum[16];
    int tid = threadIdx.x;
    int lane = tid & 31, wid = tid >> 5;
    int v = (tid < nb) ? g_bsum[tid] : 0;
    int x = v;
    #pragma unroll
    for (int o = 1; o < 32; o <<= 1) {
        int t = __shfl_up_sync(0xffffffffu, x, o);
        if (lane >= o) x += t;
    }
    if (lane == 31) wsum[wid] = x;
    __syncthreads();
    if (wid == 0) {
        int w = (lane < 16) ? wsum[lane] : 0;
        #pragma unroll
        for (int o = 1; o < 16; o <<= 1) {
            int t = __shfl_up_sync(0xffffffffu, w, o);
            if (lane >= o) w += t;
        }
        if (lane < 16) wsum[lane] = w;
    }
    __syncthreads();
    int pre = wid ? wsum[wid - 1] : 0;
    if (tid < nb) g_bsum[tid] = pre + x - v;
    if (tid == 0) g_off[n] = wsum[15];
}

__global__ void k_scan3(int n) {
    int idx = blockIdx.x * 256 + threadIdx.x;
    if (idx < n) g_off[idx] += g_bsum[blockIdx.x];
}

// ---------------- atomic-free CSR fill using precomputed ranks ----------------
__global__ void k_scatter(const int* __restrict__ src, const int* __restrict__ dst, int E) {
    int i = blockIdx.x * blockDim.x + threadIdx.x;
    int stride = gridDim.x * blockDim.x;
    for (int e = i; e < E; e += stride) {
        int d = dst[e];
        g_adj[g_off[d] + g_rank[e]] = src[e];
    }
}

// ---------------- fused round: aggregate (gather) + GEMM + epilogue ----------------
#define FMA4(AS, BV, ACC) \
    ACC[0] = fmaf(AS, BV.x, ACC[0]); \
    ACC[1] = fmaf(AS, BV.y, ACC[1]); \
    ACC[2] = fmaf(AS, BV.z, ACC[2]); \
    ACC[3] = fmaf(AS, BV.w, ACC[3]);

// which_in: 0->g_h0, 1->g_h1, 2->g_h2.  which_out: 0->g_h1, 1->g_h2, 2->g_x4 (fp32)
__global__ __launch_bounds__(256) void k_fused(
    const float* __restrict__ xtag,
    const float* __restrict__ W1l, const float* __restrict__ W2l, const float* __restrict__ W4l,
    int which_in, int which_out, int n, int do_sum)
{
    __shared__ __align__(16) float Bs[HID * HID];
    __shared__ __align__(16) float As[HID * HID];
    __shared__ float p1w[HID], p3p[HID], p3n[HID];

    const __nv_bfloat16* xh = (which_in == 0) ? g_h0 : ((which_in == 1) ? g_h1 : g_h2);
    const uint2* xr = (const uint2*)xh;   // 4 bf16 per uint2; 16 uint2 per row
    __nv_bfloat16* outh = (which_out == 0) ? g_h1 : ((which_out == 1) ? g_h2 : (__nv_bfloat16*)0);

    int tid = threadIdx.x;
    for (int i = tid; i < HID * HID; i += 256) Bs[i] = W2l[i];
    if (tid < HID) {
        p1w[tid] = W1l[tid];
        float w = W4l[tid];
        p3p[tid] = fmaxf(w, 0.f);
        p3n[tid] = fmaxf(-w, 0.f);
    }
    __syncthreads();

    int tx = tid & 15, ty = tid >> 4;      // tx: lane/h-group, ty: half-warp/node-group
    int h0 = tx * 4, m0 = ty * 4;
    float4* As4 = (float4*)As;
    float4* Bs4 = (float4*)Bs;
    float psum[4] = {0.f, 0.f, 0.f, 0.f};
    int ntiles = (n + 63) >> 6;

    for (int tile = blockIdx.x; tile < ntiles; tile += gridDim.x) {
        int base = tile << 6;

        // ---- phase A: half-warp ty aggregates nodes base+m0 .. base+m0+3 into As ----
        #pragma unroll
        for (int i = 0; i < 4; ++i) {
            int m = base + m0 + i;
            float4 acc = make_float4(0.f, 0.f, 0.f, 0.f);
            if (m < n) {
                int s = g_off[m], e = g_off[m + 1];
                int k = s;
                for (; k + 4 <= e; k += 4) {
                    int j0 = g_adj[k], j1 = g_adj[k + 1], j2 = g_adj[k + 2], j3 = g_adj[k + 3];
                    uint2 u0 = xr[j0 * 16 + tx];
                    uint2 u1 = xr[j1 * 16 + tx];
                    uint2 u2 = xr[j2 * 16 + tx];
                    uint2 u3 = xr[j3 * 16 + tx];
                    float2 a0 = bf2_to_f2(u0.x), b0 = bf2_to_f2(u0.y);
                    float2 a1 = bf2_to_f2(u1.x), b1 = bf2_to_f2(u1.y);
                    float2 a2 = bf2_to_f2(u2.x), b2 = bf2_to_f2(u2.y);
                    float2 a3 = bf2_to_f2(u3.x), b3 = bf2_to_f2(u3.y);
                    acc.x += (a0.x + a1.x) + (a2.x + a3.x);
                    acc.y += (a0.y + a1.y) + (a2.y + a3.y);
                    acc.z += (b0.x + b1.x) + (b2.x + b3.x);
                    acc.w += (b0.y + b1.y) + (b2.y + b3.y);
                }
                for (; k < e; ++k) {
                    uint2 u = xr[g_adj[k] * 16 + tx];
                    float2 a = bf2_to_f2(u.x), b = bf2_to_f2(u.y);
                    acc.x += a.x; acc.y += a.y; acc.z += b.x; acc.w += b.y;
                }
            }
            As4[(m0 + i) * 16 + tx] = acc;
        }
        __syncthreads();

        // ---- phase B: 64x64x64 register-blocked GEMM + epilogue ----
        float acc[4][4];
        #pragma unroll
        for (int i = 0; i < 4; ++i)
            #pragma unroll
            for (int j = 0; j < 4; ++j) acc[i][j] = 0.f;

        #pragma unroll
        for (int k4 = 0; k4 < 16; ++k4) {
            float4 b0 = Bs4[(4 * k4 + 0) * 16 + tx];
            float4 b1 = Bs4[(4 * k4 + 1) * 16 + tx];
            float4 b2 = Bs4[(4 * k4 + 2) * 16 + tx];
            float4 b3 = Bs4[(4 * k4 + 3) * 16 + tx];
            #pragma unroll
            for (int i = 0; i < 4; ++i) {
                float4 a = As4[(m0 + i) * 16 + k4];
                FMA4(a.x, b0, acc[i]);
                FMA4(a.y, b1, acc[i]);
                FMA4(a.z, b2, acc[i]);
                FMA4(a.w, b3, acc[i]);
            }
        }

        #pragma unroll
        for (int i = 0; i < 4; ++i) {
            int m = base + m0 + i;
            if (m < n) {
                float t = xtag[m], sp = g_spos[m], sn = g_sneg[m];
                float4 o;
                o.x = fmaxf(acc[i][0] + t * p1w[h0 + 0] + sp * p3p[h0 + 0] + sn * p3n[h0 + 0], 0.f);
                o.y = fmaxf(acc[i][1] + t * p1w[h0 + 1] + sp * p3p[h0 + 1] + sn * p3n[h0 + 1], 0.f);
                o.z = fmaxf(acc[i][2] + t * p1w[h0 + 2] + sp * p3p[h0 + 2] + sn * p3n[h0 + 2], 0.f);
                o.w = fmaxf(acc[i][3] + t * p1w[h0 + 3] + sp * p3p[h0 + 3] + sn * p3n[h0 + 3], 0.f);
                if (outh) {
                    __nv_bfloat162 pa = __floats2bfloat162_rn(o.x, o.y);
                    __nv_bfloat162 pb = __floats2bfloat162_rn(o.z, o.w);
                    uint2 u;
                    u.x = *(unsigned*)&pa;
                    u.y = *(unsigned*)&pb;
                    ((uint2*)outh)[m * 16 + tx] = u;
                } else {
                    ((float4*)g_x4)[m * 16 + tx] = o;
                }
                psum[0] += o.x; psum[1] += o.y; psum[2] += o.z; psum[3] += o.w;
            }
        }
        __syncthreads();
    }

    if (do_sum) {
        As[ty * HID + h0 + 0] = psum[0];
        As[ty * HID + h0 + 1] = psum[1];
        As[ty * HID + h0 + 2] = psum[2];
        As[ty * HID + h0 + 3] = psum[3];
        __syncthreads();
        if (tid < HID) {
            float s = 0.f;
            #pragma unroll
            for (int w = 0; w < 16; ++w) s += As[w * HID + tid];
            atomicAdd(&g_sumx[tid], s);
        }
    }
}

// ---------------- graph-pool scalar: c = sum_h relu((sumx @ W6)[h]) * W5[h] ----------------
__global__ void k_gpool(const float* __restrict__ W6, const float* __restrict__ W5) {
    int h = threadIdx.x;  // 64 threads
    float g = 0.f;
    #pragma unroll
    for (int k = 0; k < HID; ++k) g = fmaf(g_sumx[k], W6[k * HID + h], g);
    float v = fmaxf(g, 0.f) * W5[h];
    __shared__ float sh[HID];
    sh[h] = v;
    __syncthreads();
    if (h < 32) {
        float t = sh[h] + sh[h + 32];
        #pragma unroll
        for (int o = 16; o > 0; o >>= 1) t += __shfl_down_sync(0xffffffffu, t, o);
        if (h == 0) g_c[0] = t;
    }
}

// ---------------- final: Q[i] = c + sum_h relu((x @ W7)[i,h]) * W5[64+h] ----------------
__global__ __launch_bounds__(256) void k_final(
    const float* __restrict__ W7, const float* __restrict__ W5,
    float* __restrict__ Q, int n)
{
    __shared__ __align__(16) float Bs[HID * HID];
    __shared__ __align__(16) float As[HID * HID];
    __shared__ float w5s[HID];
    int tid = threadIdx.x;
    for (int i = tid; i < HID * HID; i += 256) Bs[i] = W7[i];
    if (tid < HID) w5s[tid] = W5[HID + tid];
    __syncthreads();

    int tx = tid & 15, ty = tid >> 4;
    int h0 = tx * 4, m0 = ty * 4;
    float4* As4 = (float4*)As;
    float4* Bs4 = (float4*)Bs;
    int ntiles = (n + 63) >> 6;
    float c = g_c[0];

    for (int tile = blockIdx.x; tile < ntiles; tile += gridDim.x) {
        int base = tile << 6;
        const float4* Ag = (const float4*)g_x4 + base * 16;
        int avail4 = (((n - base) < 64) ? (n - base) : 64) * 16;
        for (int i = tid; i < 1024; i += 256)
            As4[i] = (i < avail4) ? Ag[i] : make_float4(0.f, 0.f, 0.f, 0.f);
        __syncthreads();

        float acc[4][4];
        #pragma unroll
        for (int i = 0; i < 4; ++i)
            #pragma unroll
            for (int j = 0; j < 4; ++j) acc[i][j] = 0.f;

        #pragma unroll
        for (int k4 = 0; k4 < 16; ++k4) {
            float4 b0 = Bs4[(4 * k4 + 0) * 16 + tx];
            float4 b1 = Bs4[(4 * k4 + 1) * 16 + tx];
            float4 b2 = Bs4[(4 * k4 + 2) * 16 + tx];
            float4 b3 = Bs4[(4 * k4 + 3) * 16 + tx];
            #pragma unroll
            for (int i = 0; i < 4; ++i) {
                float4 a = As4[(m0 + i) * 16 + k4];
                FMA4(a.x, b0, acc[i]);
                FMA4(a.y, b1, acc[i]);
                FMA4(a.z, b2, acc[i]);
                FMA4(a.w, b3, acc[i]);
            }
        }

        #pragma unroll
        for (int i = 0; i < 4; ++i) {
            int m = base + m0 + i;
            float part = fmaxf(acc[i][0], 0.f) * w5s[h0 + 0]
                       + fmaxf(acc[i][1], 0.f) * w5s[h0 + 1]
                       + fmaxf(acc[i][2], 0.f) * w5s[h0 + 2]
                       + fmaxf(acc[i][3], 0.f) * w5s[h0 + 3];
            #pragma unroll
            for (int o = 8; o > 0; o >>= 1) part += __shfl_xor_sync(0xffffffffu, part, o);
            if (tx == 0 && m < n) Q[m] = c + part;
        }
        __syncthreads();
    }
}

// ---------------- launcher ----------------
extern "C" void kernel_launch(void* const* d_in, const int* in_sizes, int n_in,
                              void* d_out, int out_size) {
    const float* x     = (const float*)d_in[0];
    const float* xtag  = (const float*)d_in[1];
    const float* eattr = (const float*)d_in[2];
    const int*   eidx  = (const int*)d_in[3];
    const float* W1    = (const float*)d_in[4];
    const float* W2    = (const float*)d_in[5];
    const float* W4    = (const float*)d_in[6];
    const float* W5    = (const float*)d_in[7];
    const float* W6    = (const float*)d_in[8];
    const float* W7    = (const float*)d_in[9];
    float* Q = (float*)d_out;

    int n = in_sizes[1];
    int E = in_sizes[2];
    const int* src = eidx;
    const int* dst = eidx + E;

    int gb_e = (E + 255) / 256;
    int nb   = (n + 255) / 256;               // scan blocks (256 nodes each)
    int n4 = n * HID / 4;
    int gb_i = (n4 + 255) / 256;              // init covers the bigger cvt range
    int gb_g = 782;                           // fused grid (grid-stride over 64-node tiles)

    // CSR build + p3 scalars + bf16 conversion
    k_init<<<gb_i, 256>>>(x, n);
    k_hist<<<gb_e, 256>>>(src, dst, eattr, E);
    k_scan1<<<nb, 256>>>(n);
    k_scan2<<<1, 512>>>(nb, n);
    k_scan3<<<nb, 256>>>(n);
    k_scatter<<<gb_e, 256>>>(src, dst, E);

    // 4 fused propagation rounds: h0 -> h1 -> h2 -> h1 -> x4(fp32)
    k_fused<<<gb_g, 256>>>(xtag, W1 + 0 * HID, W2 + 0 * HID * HID, W4 + 0 * HID, 0, 0, n, 0);
    k_fused<<<gb_g, 256>>>(xtag, W1 + 1 * HID, W2 + 1 * HID * HID, W4 + 1 * HID, 1, 1, n, 0);
    k_fused<<<gb_g, 256>>>(xtag, W1 + 2 * HID, W2 + 2 * HID * HID, W4 + 2 * HID, 2, 0, n, 0);
    k_fused<<<gb_g, 256>>>(xtag, W1 + 3 * HID, W2 + 3 * HID * HID, W4 + 3 * HID, 1, 2, n, 1);

    // readout
    k_gpool<<<1, HID>>>(W6, W5);
    k_final<<<gb_g, 256>>>(W7, W5, Q, n);
}

// round 6
// speedup vs baseline: 1.2487x; 1.2487x over previous
#include <cuda_runtime.h>
#include <cuda_bf16.h>

#define HID 64
#define NMAX 100352
#define EMAX 3210240

// ---------------- scratch (static device globals; no allocation) ----------------
__device__ int   g_deg[NMAX];
__device__ int   g_off[NMAX + 1];
__device__ int   g_cur[NMAX];
__device__ int   g_bsum[512];
__device__ int   g_adj[EMAX];
__device__ float g_spos[NMAX];
__device__ float g_sneg[NMAX];
__device__ __align__(16) __nv_bfloat16 g_ab[NMAX * HID];          // bf16 aggregation buffer
__device__ __align__(16) __nv_bfloat16 g_h0[NMAX * HID];          // bf16 x buffers
__device__ __align__(16) __nv_bfloat16 g_h1[NMAX * HID];
__device__ __align__(16) __nv_bfloat16 g_h2[NMAX * HID];
__device__ float g_sumx[HID];
__device__ float g_c[1];

// exact bf16x2 -> float2 (bits<<16)
__device__ __forceinline__ float2 bf2_to_f2(unsigned u) {
    float2 r;
    r.x = __uint_as_float(u << 16);
    r.y = __uint_as_float(u & 0xFFFF0000u);
    return r;
}
__device__ __forceinline__ uint2 f4_to_bf4(float4 o) {
    __nv_bfloat162 a = __floats2bfloat162_rn(o.x, o.y);
    __nv_bfloat162 b = __floats2bfloat162_rn(o.z, o.w);
    uint2 u;
    u.x = *(unsigned*)&a;
    u.y = *(unsigned*)&b;
    return u;
}

// ---------------- init: zero counters + convert external fp32 x -> bf16 ----------------
__global__ void k_init(const float* __restrict__ x, int n) {
    int i = blockIdx.x * blockDim.x + threadIdx.x;
    int stride = gridDim.x * blockDim.x;
    for (int j = i; j < n; j += stride) {
        g_deg[j]  = 0;
        g_spos[j] = 0.f;
        g_sneg[j] = 0.f;
    }
    int n4 = n * (HID / 4);
    for (int j = i; j < n4; j += stride) {
        float4 f = ((const float4*)x)[j];
        ((uint2*)g_h0)[j] = f4_to_bf4(f);
    }
    if (i < HID) g_sumx[i] = 0.f;
}

// ---------------- edge pass: degree histogram + p3 scalars ----------------
__global__ void k_hist(const int* __restrict__ src, const int* __restrict__ dst,
                       const float* __restrict__ attr, int E) {
    int i = blockIdx.x * blockDim.x + threadIdx.x;
    int stride = gridDim.x * blockDim.x;
    for (int e = i; e < E; e += stride) {
        atomicAdd(&g_deg[dst[e]], 1);
        float a = attr[e];
        int s = src[e];
        if (a >= 0.f) atomicAdd(&g_spos[s], a);
        else          atomicAdd(&g_sneg[s], -a);
    }
}

// ---------------- 3-kernel parallel exclusive scan over degrees ----------------
__global__ void k_scan1(int n) {
    __shared__ int wsum[8];
    int idx = blockIdx.x * 256 + threadIdx.x;
    int lane = threadIdx.x & 31, wid = threadIdx.x >> 5;
    int v = (idx < n) ? g_deg[idx] : 0;
    int x = v;
    #pragma unroll
    for (int o = 1; o < 32; o <<= 1) {
        int t = __shfl_up_sync(0xffffffffu, x, o);
        if (lane >= o) x += t;
    }
    if (lane == 31) wsum[wid] = x;
    __syncthreads();
    if (wid == 0) {
        int w = (lane < 8) ? wsum[lane] : 0;
        #pragma unroll
        for (int o = 1; o < 8; o <<= 1) {
            int t = __shfl_up_sync(0xffffffffu, w, o);
            if (lane >= o) w += t;
        }
        if (lane < 8) wsum[lane] = w;
    }
    __syncthreads();
    int pre = wid ? wsum[wid - 1] : 0;
    if (idx < n) g_off[idx] = pre + x - v;
    if (threadIdx.x == 255) g_bsum[blockIdx.x] = pre + x;
}

__global__ void k_scan2(int nb, int n) {
    __shared__ int wsum[16];
    int tid = threadIdx.x;
    int lane = tid & 31, wid = tid >> 5;
    int v = (tid < nb) ? g_bsum[tid] : 0;
    int x = v;
    #pragma unroll
    for (int o = 1; o < 32; o <<= 1) {
        int t = __shfl_up_sync(0xffffffffu, x, o);
        if (lane >= o) x += t;
    }
    if (lane == 31) wsum[wid] = x;
    __syncthreads();
    if (wid == 0) {
        int w = (lane < 16) ? wsum[lane] : 0;
        #pragma unroll
        for (int o = 1; o < 16; o <<= 1) {
            int t = __shfl_up_sync(0xffffffffu, w, o);
            if (lane >= o) w += t;
        }
        if (lane < 16) wsum[lane] = w;
    }
    __syncthreads();
    int pre = wid ? wsum[wid - 1] : 0;
    if (tid < nb) g_bsum[tid] = pre + x - v;
    if (tid == 0) g_off[n] = wsum[15];
}

// finalize offsets + seed scatter cursors
__global__ void k_scan3(int n) {
    int idx = blockIdx.x * 256 + threadIdx.x;
    if (idx < n) {
        int v = g_off[idx] + g_bsum[blockIdx.x];
        g_off[idx] = v;
        g_cur[idx] = v;
    }
}

// ---------------- CSR fill: claim slot via cursor atomic (no rank buffer) ----------------
__global__ void k_scatter(const int* __restrict__ src, const int* __restrict__ dst, int E) {
    int i = blockIdx.x * blockDim.x + threadIdx.x;
    int stride = gridDim.x * blockDim.x;
    for (int e = i; e < E; e += stride) {
        int r = atomicAdd(&g_cur[dst[e]], 1);
        g_adj[r] = src[e];
    }
}

// ---------------- gather-side aggregation: half-warp per node, bf16 in/out ----------------
__global__ void k_aggr(const __nv_bfloat16* __restrict__ xh, int n) {
    int node = (blockIdx.x * blockDim.x + threadIdx.x) >> 4;
    if (node >= n) return;
    int lane = threadIdx.x & 15;
    const uint2* xr = (const uint2*)xh;   // 4 bf16 per uint2; 16 uint2 per row
    int s = g_off[node], e = g_off[node + 1];
    float4 acc = make_float4(0.f, 0.f, 0.f, 0.f);
    int k = s;
    for (; k + 4 <= e; k += 4) {
        int j0 = g_adj[k], j1 = g_adj[k + 1], j2 = g_adj[k + 2], j3 = g_adj[k + 3];
        uint2 u0 = xr[j0 * 16 + lane];
        uint2 u1 = xr[j1 * 16 + lane];
        uint2 u2 = xr[j2 * 16 + lane];
        uint2 u3 = xr[j3 * 16 + lane];
        float2 a0 = bf2_to_f2(u0.x), b0 = bf2_to_f2(u0.y);
        float2 a1 = bf2_to_f2(u1.x), b1 = bf2_to_f2(u1.y);
        float2 a2 = bf2_to_f2(u2.x), b2 = bf2_to_f2(u2.y);
        float2 a3 = bf2_to_f2(u3.x), b3 = bf2_to_f2(u3.y);
        acc.x += (a0.x + a1.x) + (a2.x + a3.x);
        acc.y += (a0.y + a1.y) + (a2.y + a3.y);
        acc.z += (b0.x + b1.x) + (b2.x + b3.x);
        acc.w += (b0.y + b1.y) + (b2.y + b3.y);
    }
    for (; k < e; ++k) {
        uint2 u = xr[g_adj[k] * 16 + lane];
        float2 a = bf2_to_f2(u.x), b = bf2_to_f2(u.y);
        acc.x += a.x; acc.y += a.y; acc.z += b.x; acc.w += b.y;
    }
    ((uint2*)g_ab)[node * 16 + lane] = f4_to_bf4(acc);
}

// ---------------- round GEMM: xnew = relu(p1 + aggr@W2 + p3) ----------------
#define FMA4(AS, BV, ACC) \
    ACC[0] = fmaf(AS, BV.x, ACC[0]); \
    ACC[1] = fmaf(AS, BV.y, ACC[1]); \
    ACC[2] = fmaf(AS, BV.z, ACC[2]); \
    ACC[3] = fmaf(AS, BV.w, ACC[3]);

__global__ __launch_bounds__(256) void k_round(
    const float* __restrict__ xtag,
    const float* __restrict__ W1l, const float* __restrict__ W2l, const float* __restrict__ W4l,
    __nv_bfloat16* __restrict__ outh, int n, int do_sum)
{
    __shared__ __align__(16) float Bs[HID * HID];
    __shared__ __align__(16) float As[HID * HID];
    __shared__ float p1w[HID], p3p[HID], p3n[HID];

    int tid = threadIdx.x;
    for (int i = tid; i < HID * HID; i += 256) Bs[i] = W2l[i];
    if (tid < HID) {
        p1w[tid] = W1l[tid];
        float w = W4l[tid];
        p3p[tid] = fmaxf(w, 0.f);
        p3n[tid] = fmaxf(-w, 0.f);
    }
    __syncthreads();

    int tx = tid & 15, ty = tid >> 4;
    int h0 = tx * 4, m0 = ty * 4;
    float4* As4 = (float4*)As;
    float4* Bs4 = (float4*)Bs;
    float psum[4] = {0.f, 0.f, 0.f, 0.f};
    int ntiles = (n + 63) >> 6;

    for (int tile = blockIdx.x; tile < ntiles; tile += gridDim.x) {
        int base = tile << 6;
        const uint2* Ag = (const uint2*)g_ab + base * 16;
        int avail = (((n - base) < 64) ? (n - base) : 64) * 16;
        for (int i = tid; i < 1024; i += 256) {
            float4 v = make_float4(0.f, 0.f, 0.f, 0.f);
            if (i < avail) {
                uint2 u = Ag[i];
                float2 a = bf2_to_f2(u.x), b = bf2_to_f2(u.y);
                v = make_float4(a.x, a.y, b.x, b.y);
            }
            As4[i] = v;
        }
        __syncthreads();

        float acc[4][4];
        #pragma unroll
        for (int i = 0; i < 4; ++i)
            #pragma unroll
            for (int j = 0; j < 4; ++j) acc[i][j] = 0.f;

        #pragma unroll
        for (int k4 = 0; k4 < 16; ++k4) {
            float4 b0 = Bs4[(4 * k4 + 0) * 16 + tx];
            float4 b1 = Bs4[(4 * k4 + 1) * 16 + tx];
            float4 b2 = Bs4[(4 * k4 + 2) * 16 + tx];
            float4 b3 = Bs4[(4 * k4 + 3) * 16 + tx];
            #pragma unroll
            for (int i = 0; i < 4; ++i) {
                float4 a = As4[(m0 + i) * 16 + k4];
                FMA4(a.x, b0, acc[i]);
                FMA4(a.y, b1, acc[i]);
                FMA4(a.z, b2, acc[i]);
                FMA4(a.w, b3, acc[i]);
            }
        }

        #pragma unroll
        for (int i = 0; i < 4; ++i) {
            int m = base + m0 + i;
            if (m < n) {
                float t = xtag[m], sp = g_spos[m], sn = g_sneg[m];
                float4 o;
                o.x = fmaxf(acc[i][0] + t * p1w[h0 + 0] + sp * p3p[h0 + 0] + sn * p3n[h0 + 0], 0.f);
                o.y = fmaxf(acc[i][1] + t * p1w[h0 + 1] + sp * p3p[h0 + 1] + sn * p3n[h0 + 1], 0.f);
                o.z = fmaxf(acc[i][2] + t * p1w[h0 + 2] + sp * p3p[h0 + 2] + sn * p3n[h0 + 2], 0.f);
                o.w = fmaxf(acc[i][3] + t * p1w[h0 + 3] + sp * p3p[h0 + 3] + sn * p3n[h0 + 3], 0.f);
                ((uint2*)outh)[m * 16 + tx] = f4_to_bf4(o);
                psum[0] += o.x; psum[1] += o.y; psum[2] += o.z; psum[3] += o.w;
            }
        }
        __syncthreads();
    }

    if (do_sum) {
        As[ty * HID + h0 + 0] = psum[0];
        As[ty * HID + h0 + 1] = psum[1];
        As[ty * HID + h0 + 2] = psum[2];
        As[ty * HID + h0 + 3] = psum[3];
        __syncthreads();
        if (tid < HID) {
            float s = 0.f;
            #pragma unroll
            for (int w = 0; w < 16; ++w) s += As[w * HID + tid];
            atomicAdd(&g_sumx[tid], s);
        }
    }
}

// ---------------- graph-pool scalar: c = sum_h relu((sumx @ W6)[h]) * W5[h] ----------------
__global__ void k_gpool(const float* __restrict__ W6, const float* __restrict__ W5) {
    int h = threadIdx.x;  // 64 threads
    float g = 0.f;
    #pragma unroll
    for (int k = 0; k < HID; ++k) g = fmaf(g_sumx[k], W6[k * HID + h], g);
    float v = fmaxf(g, 0.f) * W5[h];
    __shared__ float sh[HID];
    sh[h] = v;
    __syncthreads();
    if (h < 32) {
        float t = sh[h] + sh[h + 32];
        #pragma unroll
        for (int o = 16; o > 0; o >>= 1) t += __shfl_down_sync(0xffffffffu, t, o);
        if (h == 0) g_c[0] = t;
    }
}

// ---------------- final: Q[i] = c + sum_h relu((x @ W7)[i,h]) * W5[64+h] ----------------
__global__ __launch_bounds__(256) void k_final(
    const float* __restrict__ W7, const float* __restrict__ W5,
    float* __restrict__ Q, int n)
{
    __shared__ __align__(16) float Bs[HID * HID];
    __shared__ __align__(16) float As[HID * HID];
    __shared__ float w5s[HID];
    int tid = threadIdx.x;
    for (int i = tid; i < HID * HID; i += 256) Bs[i] = W7[i];
    if (tid < HID) w5s[tid] = W5[HID + tid];
    __syncthreads();

    int tx = tid & 15, ty = tid >> 4;
    int h0 = tx * 4, m0 = ty * 4;
    float4* As4 = (float4*)As;
    float4* Bs4 = (float4*)Bs;
    int ntiles = (n + 63) >> 6;
    float c = g_c[0];

    for (int tile = blockIdx.x; tile < ntiles; tile += gridDim.x) {
        int base = tile << 6;
        const uint2* Ag = (const uint2*)g_h1 + base * 16;
        int avail = (((n - base) < 64) ? (n - base) : 64) * 16;
        for (int i = tid; i < 1024; i += 256) {
            float4 v = make_float4(0.f, 0.f, 0.f, 0.f);
            if (i < avail) {
                uint2 u = Ag[i];
                float2 a = bf2_to_f2(u.x), b = bf2_to_f2(u.y);
                v = make_float4(a.x, a.y, b.x, b.y);
            }
            As4[i] = v;
        }
        __syncthreads();

        float acc[4][4];
        #pragma unroll
        for (int i = 0; i < 4; ++i)
            #pragma unroll
            for (int j = 0; j < 4; ++j) acc[i][j] = 0.f;

        #pragma unroll
        for (int k4 = 0; k4 < 16; ++k4) {
            float4 b0 = Bs4[(4 * k4 + 0) * 16 + tx];
            float4 b1 = Bs4[(4 * k4 + 1) * 16 + tx];
            float4 b2 = Bs4[(4 * k4 + 2) * 16 + tx];
            float4 b3 = Bs4[(4 * k4 + 3) * 16 + tx];
            #pragma unroll
            for (int i = 0; i < 4; ++i) {
                float4 a = As4[(m0 + i) * 16 + k4];
                FMA4(a.x, b0, acc[i]);
                FMA4(a.y, b1, acc[i]);
                FMA4(a.z, b2, acc[i]);
                FMA4(a.w, b3, acc[i]);
            }
        }

        #pragma unroll
        for (int i = 0; i < 4; ++i) {
            int m = base + m0 + i;
            float part = fmaxf(acc[i][0], 0.f) * w5s[h0 + 0]
                       + fmaxf(acc[i][1], 0.f) * w5s[h0 + 1]
                       + fmaxf(acc[i][2], 0.f) * w5s[h0 + 2]
                       + fmaxf(acc[i][3], 0.f) * w5s[h0 + 3];
            #pragma unroll
            for (int o = 8; o > 0; o >>= 1) part += __shfl_xor_sync(0xffffffffu, part, o);
            if (tx == 0 && m < n) Q[m] = c + part;
        }
        __syncthreads();
    }
}

// ---------------- launcher ----------------
extern "C" void kernel_launch(void* const* d_in, const int* in_sizes, int n_in,
                              void* d_out, int out_size) {
    const float* x     = (const float*)d_in[0];
    const float* xtag  = (const float*)d_in[1];
    const float* eattr = (const float*)d_in[2];
    const int*   eidx  = (const int*)d_in[3];
    const float* W1    = (const float*)d_in[4];
    const float* W2    = (const float*)d_in[5];
    const float* W4    = (const float*)d_in[6];
    const float* W5    = (const float*)d_in[7];
    const float* W6    = (const float*)d_in[8];
    const float* W7    = (const float*)d_in[9];
    float* Q = (float*)d_out;

    int n = in_sizes[1];
    int E = in_sizes[2];
    const int* src = eidx;
    const int* dst = eidx + E;

    int gb_e = (E + 255) / 256;
    int nb   = (n + 255) / 256;               // scan blocks (256 nodes each)
    int n4 = n * HID / 4;
    int gb_i = (n4 + 255) / 256;
    int gb_hw = (n * 16 + 255) / 256;         // half-warp-per-node
    int gb_g = 782;                            // GEMM grid

    // CSR build + p3 scalars + bf16 conversion
    k_init<<<gb_i, 256>>>(x, n);
    k_hist<<<gb_e, 256>>>(src, dst, eattr, E);
    k_scan1<<<nb, 256>>>(n);
    k_scan2<<<1, 512>>>(nb, n);
    k_scan3<<<nb, 256>>>(n);
    k_scatter<<<gb_e, 256>>>(src, dst, E);

    // 4 propagation rounds: h0 -> h1 -> h2 -> h0 -> h1
    __nv_bfloat16 *h0, *h1, *h2;
    cudaGetSymbolAddress((void**)&h0, g_h0);
    cudaGetSymbolAddress((void**)&h1, g_h1);
    cudaGetSymbolAddress((void**)&h2, g_h2);

    k_aggr<<<gb_hw, 256>>>(h0, n);
    k_round<<<gb_g, 256>>>(xtag, W1 + 0 * HID, W2 + 0 * HID * HID, W4 + 0 * HID, h1, n, 0);
    k_aggr<<<gb_hw, 256>>>(h1, n);
    k_round<<<gb_g, 256>>>(xtag, W1 + 1 * HID, W2 + 1 * HID * HID, W4 + 1 * HID, h2, n, 0);
    k_aggr<<<gb_hw, 256>>>(h2, n);
    k_round<<<gb_g, 256>>>(xtag, W1 + 2 * HID, W2 + 2 * HID * HID, W4 + 2 * HID, h0, n, 0);
    k_aggr<<<gb_hw, 256>>>(h0, n);
    k_round<<<gb_g, 256>>>(xtag, W1 + 3 * HID, W2 + 3 * HID * HID, W4 + 3 * HID, h1, n, 1);

    // readout
    k_gpool<<<1, HID>>>(W6, W5);
    k_final<<<gb_g, 256>>>(W7, W5, Q, n);
}